// round 2
// baseline (speedup 1.0000x reference)
#include <cuda_runtime.h>
#include <cstdint>

// ----------------------------------------------------------------------------
// MinkowskiUNetBackbone: two sparse-conv layers with ReLU between.
//   h   = scatter_add(mask * (feats[in_idx] @ W_in[k]))    [N, 64]
//   out = scatter_add(mask * (relu(h)[in_idx] @ W_out[k])) [N, 32]
// Indices are INT32 on device (JAX x64-disabled downcasts the requested int64).
// Warp-per-pair; one kernel offset k per blockIdx.y so W_k lives in registers.
// Packed f32x2 FMA for the GEMV; red.global.add.v2.f32 scatter for layer 1.
// ----------------------------------------------------------------------------

constexpr int CIN  = 32;
constexpr int CMID = 64;
constexpr int COUT = 32;
constexpr int MAXN = 210000;   // N = 200000 here; margin

// Scratch for the hidden layer (alloc-free rule: __device__ global array).
__device__ float g_h[(size_t)MAXN * CMID];

static __device__ __forceinline__ unsigned long long pk2(float x, float y) {
    unsigned long long r;
    asm("mov.b64 %0, {%1, %2};" : "=l"(r) : "f"(x), "f"(y));
    return r;
}
static __device__ __forceinline__ float2 upk2(unsigned long long v) {
    float2 f;
    asm("mov.b64 {%0, %1}, %2;" : "=f"(f.x), "=f"(f.y) : "l"(v));
    return f;
}
// Packed f32x2 FMA (Blackwell): d = a*b + c elementwise on packed pairs.
static __device__ __forceinline__ unsigned long long fma2(
    unsigned long long a, unsigned long long b, unsigned long long c) {
    unsigned long long d;
    asm("fma.rn.f32x2 %0, %1, %2, %3;" : "=l"(d) : "l"(a), "l"(b), "l"(c));
    return d;
}
// Vectorized global reduction (no return): 2 contiguous floats per op.
static __device__ __forceinline__ void red_add_v2(float* p, float x, float y) {
    asm volatile("red.global.add.v2.f32 [%0], {%1, %2};"
                 :: "l"(p), "f"(x), "f"(y) : "memory");
}

// ---------------------------------------------------------------------------
// Zero the hidden buffer and the output (d_out is poisoned by the harness).
// ---------------------------------------------------------------------------
__global__ void zero_kernel(float4* __restrict__ out, int n_out4, int n_h4) {
    int i = blockIdx.x * blockDim.x + threadIdx.x;
    float4 z = make_float4(0.f, 0.f, 0.f, 0.f);
    if (i < n_out4) out[i] = z;
    if (i < n_h4) reinterpret_cast<float4*>(g_h)[i] = z;
}

// ---------------------------------------------------------------------------
// Layer 1: h[out] += mask * feats[in] @ W_in[k]   (32 -> 64)
// One warp per pair. Lane j owns output columns {2j, 2j+1} of W_in[k]
// held in 32 packed registers. x broadcast across the warp via shfl.
// ---------------------------------------------------------------------------
__global__ __launch_bounds__(256) void layer1_kernel(
    const float* __restrict__ feats,
    const int*  __restrict__ in_idx,
    const int*  __restrict__ out_idx,
    const float* __restrict__ mask,
    const float* __restrict__ W_in,
    int P)
{
    const int k    = blockIdx.y;
    const int lane = threadIdx.x & 31;
    const int warp = threadIdx.x >> 5;

    // Lane's two weight columns: W_in[k][c][2*lane .. 2*lane+1]
    const float2* Wk = reinterpret_cast<const float2*>(W_in + (size_t)k * CIN * CMID);
    unsigned long long Wc[CIN];
#pragma unroll
    for (int c = 0; c < CIN; c++) {
        float2 w = Wk[c * (CMID / 2) + lane];
        Wc[c] = pk2(w.x, w.y);
    }

    const int*   ii = in_idx  + (size_t)k * P;
    const int*   oi = out_idx + (size_t)k * P;
    const float* mk = mask    + (size_t)k * P;

    const int wid = blockIdx.x * 8 + warp;
    const int nw  = gridDim.x * 8;

    for (int p = wid; p < P; p += nw) {
        if (mk[p] <= 0.5f) continue;                       // warp-uniform
        const int vin  = ii[p];
        const int vout = oi[p];

        const float x = feats[(size_t)vin * CIN + lane];   // 128B coalesced gather
        unsigned long long acc = 0ull;                     // {0.f, 0.f}
#pragma unroll
        for (int c = 0; c < CIN; c++) {
            float xc = __shfl_sync(0xffffffffu, x, c);
            acc = fma2(pk2(xc, xc), Wc[c], acc);
        }
        float2 a = upk2(acc);
        red_add_v2(g_h + (size_t)vout * CMID + 2 * lane, a.x, a.y);
    }
}

// ---------------------------------------------------------------------------
// Layer 2: out[o] += mask * relu(h[in]) @ W_out[k]   (64 -> 32)
// One warp per pair. Lane j owns output column j; W column packed over c
// pairs into 32 u64 registers. ReLU fused into the gather.
// ---------------------------------------------------------------------------
__global__ __launch_bounds__(256) void layer2_kernel(
    const int*  __restrict__ in_idx,
    const int*  __restrict__ out_idx,
    const float* __restrict__ mask,
    const float* __restrict__ W_out,
    float* __restrict__ out,
    int P)
{
    const int k    = blockIdx.y;
    const int lane = threadIdx.x & 31;
    const int warp = threadIdx.x >> 5;

    // Lane holds W_out[k][c][lane] for c = 0..63, packed over (2c, 2c+1).
    const float* Wk = W_out + (size_t)k * CMID * COUT;
    unsigned long long Wc[CMID / 2];
#pragma unroll
    for (int c2 = 0; c2 < CMID / 2; c2++) {
        float w0 = Wk[(2 * c2)     * COUT + lane];
        float w1 = Wk[(2 * c2 + 1) * COUT + lane];
        Wc[c2] = pk2(w0, w1);
    }

    const int*   ii = in_idx  + (size_t)k * P;
    const int*   oi = out_idx + (size_t)k * P;
    const float* mk = mask    + (size_t)k * P;

    const int wid = blockIdx.x * 8 + warp;
    const int nw  = gridDim.x * 8;

    for (int p = wid; p < P; p += nw) {
        if (mk[p] <= 0.5f) continue;
        const int vin  = ii[p];
        const int vout = oi[p];

        const float h0 = fmaxf(g_h[(size_t)vin * CMID + lane],      0.f);
        const float h1 = fmaxf(g_h[(size_t)vin * CMID + 32 + lane], 0.f);

        unsigned long long acc = 0ull;
#pragma unroll
        for (int c2 = 0; c2 < 16; c2++) {
            float xa = __shfl_sync(0xffffffffu, h0, 2 * c2);
            float xb = __shfl_sync(0xffffffffu, h0, 2 * c2 + 1);
            acc = fma2(pk2(xa, xb), Wc[c2], acc);
        }
#pragma unroll
        for (int c2 = 16; c2 < 32; c2++) {
            float xa = __shfl_sync(0xffffffffu, h1, 2 * c2 - 32);
            float xb = __shfl_sync(0xffffffffu, h1, 2 * c2 - 31);
            acc = fma2(pk2(xa, xb), Wc[c2], acc);
        }
        float2 a = upk2(acc);
        atomicAdd(out + (size_t)vout * COUT + lane, a.x + a.y);  // -> RED.F32
    }
}

// ---------------------------------------------------------------------------
// Inputs (metadata order): feats f32[N,32], nbr_in_idx i32[K,P],
// nbr_out_idx i32[K,P], nbr_mask f32[K,P], W_in f32[K,32,64], W_out f32[K,64,32]
// Output: f32[N,32]
// ---------------------------------------------------------------------------
extern "C" void kernel_launch(void* const* d_in, const int* in_sizes, int n_in,
                              void* d_out, int out_size) {
    const float* feats   = (const float*)d_in[0];
    const int*   in_idx  = (const int*)  d_in[1];
    const int*   out_idx = (const int*)  d_in[2];
    const float* mask    = (const float*)d_in[3];
    const float* W_in    = (const float*)d_in[4];
    const float* W_out   = (const float*)d_in[5];
    float*       out     = (float*)      d_out;

    const int N = in_sizes[0] / CIN;
    const int K = in_sizes[4] / (CIN * CMID);
    const int P = in_sizes[3] / K;

    // Zero out (poisoned) and hidden buffer.
    const int n_out4 = N * COUT / 4;
    const int n_h4   = N * CMID / 4;
    const int nmax   = (n_out4 > n_h4) ? n_out4 : n_h4;
    zero_kernel<<<(nmax + 255) / 256, 256>>>((float4*)out, n_out4, n_h4);

    dim3 grid1(64, K);
    layer1_kernel<<<grid1, 256>>>(feats, in_idx, out_idx, mask, W_in, P);

    dim3 grid2(64, K);
    layer2_kernel<<<grid2, 256>>>(in_idx, out_idx, mask, W_out, out, P);
}

// round 5
// speedup vs baseline: 1.3322x; 1.3322x over previous
#include <cuda_runtime.h>
#include <cstdint>

// ----------------------------------------------------------------------------
// Dense-precompute formulation, K-chunked (9 offsets per chunk) to keep
// __device__ statics small (~0.6 GB total):
//   for each chunk of 9 k's:
//     Y[k] = feats @ W_in[k]          (dense GEMM, no gather)
//     g_h[vout] += Y[k][vin]          (streaming scatter over valid pairs of k)
//   then same with relu(g_h) @ W_out[k] -> out.
// Same FLOPs as gathered form (each voxel used ~1x per k after masking), but
// GEMMs are regular/coalesced and scatters are pure float4-copy + red.v4.
// ----------------------------------------------------------------------------

constexpr int CIN   = 32;
constexpr int CMID  = 64;
constexpr int COUT  = 32;
constexpr int MAXN  = 200192;
constexpr int MAXK  = 27;
constexpr int MAXP  = 400000;
constexpr int KCH   = 9;          // k's per chunk (27 = 3 * 9)

__device__ float g_h[(size_t)MAXN * CMID];                 //  51 MB
__device__ float g_Y[(size_t)KCH * MAXN * CMID];           // 461 MB (chunk buffer)
__device__ uint2 g_pairs[(size_t)MAXK * MAXP];             //  86 MB (per-k segments)
__device__ int   g_cnt[MAXK];

static __device__ __forceinline__ unsigned long long pk2(float x, float y) {
    unsigned long long r;
    asm("mov.b64 %0, {%1, %2};" : "=l"(r) : "f"(x), "f"(y));
    return r;
}
static __device__ __forceinline__ unsigned long long fma2(
    unsigned long long a, unsigned long long b, unsigned long long c) {
    unsigned long long d;
    asm("fma.rn.f32x2 %0, %1, %2, %3;" : "=l"(d) : "l"(a), "l"(b), "l"(c));
    return d;
}
static __device__ __forceinline__ void red_add_v4(float* p, float4 v) {
    asm volatile("red.global.add.v4.f32 [%0], {%1, %2, %3, %4};"
                 :: "l"(p), "f"(v.x), "f"(v.y), "f"(v.z), "f"(v.w) : "memory");
}

// ---------------------------------------------------------------------------
__global__ void zero_kernel(float4* __restrict__ out, int n_out4, int n_h4) {
    int i = blockIdx.x * blockDim.x + threadIdx.x;
    float4 z = make_float4(0.f, 0.f, 0.f, 0.f);
    if (i < n_out4) out[i] = z;
    if (i < n_h4) reinterpret_cast<float4*>(g_h)[i] = z;
    if (i < MAXK) g_cnt[i] = 0;
}

// ---------------------------------------------------------------------------
// Compact valid pairs into per-k segments: g_pairs[k*MAXP + pos] = {vin, vout}.
// Warp-aggregated atomic on g_cnt[k] (k is warp-uniform = blockIdx.y).
// ---------------------------------------------------------------------------
__global__ __launch_bounds__(256) void compact_kernel(
    const int* __restrict__ in_idx, const int* __restrict__ out_idx,
    const float* __restrict__ mask, int P)
{
    const int k = blockIdx.y;
    const int p = blockIdx.x * blockDim.x + threadIdx.x;
    bool v = false; int vin = 0, vout = 0;
    if (p < P) {
        size_t o = (size_t)k * P + p;
        v = mask[o] > 0.5f;
        if (v) { vin = in_idx[o]; vout = out_idx[o]; }
    }
    unsigned b = __ballot_sync(0xffffffffu, v);
    int cnt = __popc(b);
    if (cnt == 0) return;
    const int lane = threadIdx.x & 31;
    const int leader = __ffs(b) - 1;
    int base = 0;
    if (lane == leader) base = atomicAdd(&g_cnt[k], cnt);
    base = __shfl_sync(0xffffffffu, base, leader);
    if (v) {
        int off = __popc(b & ((1u << lane) - 1u));
        g_pairs[(size_t)k * MAXP + base + off] =
            make_uint2((unsigned)vin, (unsigned)vout);
    }
}

// ---------------------------------------------------------------------------
// GEMM1: Y[ky][n][:] = feats[n][:] @ W_in[k0+ky]  (32 -> 64). Thread-per-voxel,
// 64-thread blocks. x staged coalesced -> smem (pad 33); W broadcast from smem;
// output flushed via padded smem tile in 2 halves -> coalesced float2 stores.
// ---------------------------------------------------------------------------
__global__ __launch_bounds__(64) void gemm1_kernel(
    const float* __restrict__ feats, const float* __restrict__ W_in,
    int N, int k0)
{
    const int ky   = blockIdx.y;
    const int k    = k0 + ky;
    const int base = blockIdx.x * 64;
    const int t    = threadIdx.x;

    __shared__ float  sx[64 * 33];
    __shared__ float2 sw[CIN * 32];
    __shared__ float2 so[64 * 17];

    {
        const float2* Wk = reinterpret_cast<const float2*>(W_in + (size_t)k * CIN * CMID);
        for (int i = t; i < CIN * 32; i += 64) sw[i] = Wk[i];
    }
    const int nv = min(64, N - base);
    for (int i = t; i < 64 * 32; i += 64) {
        float v = (i < nv * 32) ? feats[(size_t)base * 32 + i] : 0.f;
        sx[(i >> 5) * 33 + (i & 31)] = v;
    }
    __syncthreads();

    unsigned long long acc[32];
#pragma unroll
    for (int i = 0; i < 32; i++) acc[i] = 0ull;

    const float* xr = sx + t * 33;
#pragma unroll
    for (int c = 0; c < 32; c++) {
        const float xc = xr[c];
        const unsigned long long a = pk2(xc, xc);
        const ulonglong2* wrow = reinterpret_cast<const ulonglong2*>(sw + c * 32);
#pragma unroll
        for (int d = 0; d < 16; d++) {
            ulonglong2 w2 = wrow[d];
            acc[2 * d]     = fma2(a, w2.x, acc[2 * d]);
            acc[2 * d + 1] = fma2(a, w2.y, acc[2 * d + 1]);
        }
    }

    float* Yk = g_Y + ((size_t)ky * N + base) * CMID;
#pragma unroll
    for (int h = 0; h < 2; h++) {
        __syncthreads();
        float2* myrow = so + t * 17;
#pragma unroll
        for (int d = 0; d < 16; d++) {
            unsigned long long u = acc[h * 16 + d];
            float2 f; asm("mov.b64 {%0, %1}, %2;" : "=f"(f.x), "=f"(f.y) : "l"(u));
            myrow[d] = f;
        }
        __syncthreads();
        for (int i = t; i < 64 * 16; i += 64) {
            int r = i >> 4, c2 = i & 15;
            if (r < nv)
                reinterpret_cast<float2*>(Yk + (size_t)r * CMID + h * 32)[c2] =
                    so[r * 17 + c2];
        }
    }
}

// ---------------------------------------------------------------------------
// GEMM2: Y[ky][n][:] = relu(g_h[n][:]) @ W_out[k0+ky]  (64 -> 32).
// ---------------------------------------------------------------------------
__global__ __launch_bounds__(64) void gemm2_kernel(
    const float* __restrict__ W_out, int N, int k0)
{
    const int ky   = blockIdx.y;
    const int k    = k0 + ky;
    const int base = blockIdx.x * 64;
    const int t    = threadIdx.x;

    __shared__ float  sx[64 * 65];
    __shared__ float2 sw[CMID * 16];
    __shared__ float2 so[64 * 17];

    {
        const float2* Wk = reinterpret_cast<const float2*>(W_out + (size_t)k * CMID * COUT);
        for (int i = t; i < CMID * 16; i += 64) sw[i] = Wk[i];
    }
    const int nv = min(64, N - base);
    for (int i = t; i < 64 * 64; i += 64) {
        float v = (i < nv * 64) ? g_h[(size_t)base * 64 + i] : 0.f;
        sx[(i >> 6) * 65 + (i & 63)] = fmaxf(v, 0.f);   // fused ReLU
    }
    __syncthreads();

    unsigned long long acc[16];
#pragma unroll
    for (int i = 0; i < 16; i++) acc[i] = 0ull;

    const float* xr = sx + t * 65;
#pragma unroll
    for (int c = 0; c < 64; c++) {
        const float xc = xr[c];
        const unsigned long long a = pk2(xc, xc);
        const ulonglong2* wrow = reinterpret_cast<const ulonglong2*>(sw + c * 16);
#pragma unroll
        for (int d = 0; d < 8; d++) {
            ulonglong2 w2 = wrow[d];
            acc[2 * d]     = fma2(a, w2.x, acc[2 * d]);
            acc[2 * d + 1] = fma2(a, w2.y, acc[2 * d + 1]);
        }
    }

    __syncthreads();
    {
        float2* myrow = so + t * 17;
#pragma unroll
        for (int d = 0; d < 16; d++) {
            unsigned long long u = acc[d];
            float2 f; asm("mov.b64 {%0, %1}, %2;" : "=f"(f.x), "=f"(f.y) : "l"(u));
            myrow[d] = f;
        }
    }
    __syncthreads();
    float* Yk = g_Y + ((size_t)ky * N + base) * COUT;
    for (int i = t; i < 64 * 16; i += 64) {
        int r = i >> 4, c2 = i & 15;
        if (r < nv)
            reinterpret_cast<float2*>(Yk + (size_t)r * COUT)[c2] = so[r * 17 + c2];
    }
}

// ---------------------------------------------------------------------------
// Scatter1: g_h[dst][0:64] += Y[ky][src][0:64]. Half-warp per pair, red.v4.
// One k per blockIdx.y (chunk-local).
// ---------------------------------------------------------------------------
__global__ __launch_bounds__(256) void scatter1_kernel(int N, int k0) {
    const int ky   = blockIdx.y;
    const int cnt  = g_cnt[k0 + ky];
    const uint2* pairs = g_pairs + (size_t)(k0 + ky) * MAXP;
    const float* Yk    = g_Y + (size_t)ky * N * CMID;

    const int lane = threadIdx.x & 31;
    const int g    = lane >> 4;          // half-warp id
    const int l    = lane & 15;          // float4 slot within 64-ch row
    const int wid  = (blockIdx.x * 8) + (threadIdx.x >> 5);
    const int nw   = gridDim.x * 8;

    for (int i = wid * 2 + g; i < cnt; i += nw * 2) {
        uint2 pr = pairs[i];
        float4 v = reinterpret_cast<const float4*>(Yk + (size_t)pr.x * CMID)[l];
        red_add_v4(g_h + (size_t)pr.y * CMID + l * 4, v);
    }
}

// ---------------------------------------------------------------------------
// Scatter2: out[dst][0:32] += Y[ky][src][0:32]. 8 lanes per pair, red.v4.
// ---------------------------------------------------------------------------
__global__ __launch_bounds__(256) void scatter2_kernel(
    float* __restrict__ out, int N, int k0)
{
    const int ky   = blockIdx.y;
    const int cnt  = g_cnt[k0 + ky];
    const uint2* pairs = g_pairs + (size_t)(k0 + ky) * MAXP;
    const float* Yk    = g_Y + (size_t)ky * N * COUT;

    const int lane = threadIdx.x & 31;
    const int g    = lane >> 3;          // quarter-warp id
    const int l    = lane & 7;           // float4 slot within 32-ch row
    const int wid  = (blockIdx.x * 8) + (threadIdx.x >> 5);
    const int nw   = gridDim.x * 8;

    for (int i = wid * 4 + g; i < cnt; i += nw * 4) {
        uint2 pr = pairs[i];
        float4 v = reinterpret_cast<const float4*>(Yk + (size_t)pr.x * COUT)[l];
        red_add_v4(out + (size_t)pr.y * COUT + l * 4, v);
    }
}

// ---------------------------------------------------------------------------
// Inputs: feats f32[N,32], nbr_in_idx i32[K,P], nbr_out_idx i32[K,P],
// nbr_mask f32[K,P], W_in f32[K,32,64], W_out f32[K,64,32]. Output f32[N,32].
// ---------------------------------------------------------------------------
extern "C" void kernel_launch(void* const* d_in, const int* in_sizes, int n_in,
                              void* d_out, int out_size) {
    const float* feats   = (const float*)d_in[0];
    const int*   in_idx  = (const int*)  d_in[1];
    const int*   out_idx = (const int*)  d_in[2];
    const float* mask    = (const float*)d_in[3];
    const float* W_in    = (const float*)d_in[4];
    const float* W_out   = (const float*)d_in[5];
    float*       out     = (float*)      d_out;

    const int N = in_sizes[0] / CIN;
    const int K = in_sizes[4] / (CIN * CMID);
    const int P = in_sizes[3] / K;

    const int n_out4 = N * COUT / 4;
    const int n_h4   = N * CMID / 4;
    const int nmax   = (n_out4 > n_h4) ? n_out4 : n_h4;
    zero_kernel<<<(nmax + 255) / 256, 256>>>((float4*)out, n_out4, n_h4);

    dim3 gc((P + 255) / 256, K);
    compact_kernel<<<gc, 256>>>(in_idx, out_idx, mask, P);

    // Layer 1, chunked over K.
    for (int k0 = 0; k0 < K; k0 += KCH) {
        const int kc = (K - k0 < KCH) ? (K - k0) : KCH;
        dim3 gg((N + 63) / 64, kc);
        gemm1_kernel<<<gg, 64>>>(feats, W_in, N, k0);
        dim3 gs(256, kc);
        scatter1_kernel<<<gs, 256>>>(N, k0);
    }

    // Layer 2, chunked over K.
    for (int k0 = 0; k0 < K; k0 += KCH) {
        const int kc = (K - k0 < KCH) ? (K - k0) : KCH;
        dim3 gg((N + 63) / 64, kc);
        gemm2_kernel<<<gg, 64>>>(W_out, N, k0);
        dim3 gs(256, kc);
        scatter2_kernel<<<gs, 256>>>(out, N, k0);
    }
}

// round 6
// speedup vs baseline: 1.5450x; 1.1597x over previous
#include <cuda_runtime.h>
#include <cstdint>

// ----------------------------------------------------------------------------
// Fully fused sparse conv: per block = 64 pairs of one offset k.
//   gather x rows -> smem  ->  register-tiled GEMV (f32x2)  ->  red.v4 scatter
// No intermediate Y buffer at all (it was a pure DRAM round-trip: each Y row
// is consumed ~once). Statics: g_h 51MB + g_pairs 86MB.
// ----------------------------------------------------------------------------

constexpr int CIN   = 32;
constexpr int CMID  = 64;
constexpr int COUT  = 32;
constexpr int MAXN  = 200192;
constexpr int MAXK  = 27;
constexpr int MAXP  = 400000;

__device__ float g_h[(size_t)MAXN * CMID];        // 51 MB hidden layer
__device__ uint2 g_pairs[(size_t)MAXK * MAXP];    // 86 MB per-k pair segments
__device__ int   g_cnt[MAXK];

static __device__ __forceinline__ unsigned long long pk2(float x, float y) {
    unsigned long long r;
    asm("mov.b64 %0, {%1, %2};" : "=l"(r) : "f"(x), "f"(y));
    return r;
}
static __device__ __forceinline__ float2 upk2(unsigned long long v) {
    float2 f;
    asm("mov.b64 {%0, %1}, %2;" : "=f"(f.x), "=f"(f.y) : "l"(v));
    return f;
}
static __device__ __forceinline__ unsigned long long fma2(
    unsigned long long a, unsigned long long b, unsigned long long c) {
    unsigned long long d;
    asm("fma.rn.f32x2 %0, %1, %2, %3;" : "=l"(d) : "l"(a), "l"(b), "l"(c));
    return d;
}
static __device__ __forceinline__ void red_add_v4(float* p, float4 v) {
    asm volatile("red.global.add.v4.f32 [%0], {%1, %2, %3, %4};"
                 :: "l"(p), "f"(v.x), "f"(v.y), "f"(v.z), "f"(v.w) : "memory");
}

// ---------------------------------------------------------------------------
__global__ void zero_kernel(float4* __restrict__ out, int n_out4, int n_h4) {
    int i = blockIdx.x * blockDim.x + threadIdx.x;
    float4 z = make_float4(0.f, 0.f, 0.f, 0.f);
    if (i < n_out4) out[i] = z;
    if (i < n_h4) reinterpret_cast<float4*>(g_h)[i] = z;
    if (i < MAXK) g_cnt[i] = 0;
}

// ---------------------------------------------------------------------------
// Compact valid pairs into per-k segments (warp-aggregated atomic).
// ---------------------------------------------------------------------------
__global__ __launch_bounds__(256) void compact_kernel(
    const int* __restrict__ in_idx, const int* __restrict__ out_idx,
    const float* __restrict__ mask, int P)
{
    const int k = blockIdx.y;
    const int p = blockIdx.x * blockDim.x + threadIdx.x;
    bool v = false; int vin = 0, vout = 0;
    if (p < P) {
        size_t o = (size_t)k * P + p;
        v = mask[o] > 0.5f;
        if (v) { vin = in_idx[o]; vout = out_idx[o]; }
    }
    unsigned b = __ballot_sync(0xffffffffu, v);
    int cnt = __popc(b);
    if (cnt == 0) return;
    const int lane = threadIdx.x & 31;
    const int leader = __ffs(b) - 1;
    int base = 0;
    if (lane == leader) base = atomicAdd(&g_cnt[k], cnt);
    base = __shfl_sync(0xffffffffu, base, leader);
    if (v) {
        int off = __popc(b & ((1u << lane) - 1u));
        g_pairs[(size_t)k * MAXP + base + off] =
            make_uint2((unsigned)vin, (unsigned)vout);
    }
}

// ---------------------------------------------------------------------------
// Fused layer 1: for 64 pairs of offset k:
//   g_h[vout][0:64] += feats[vin][0:32] @ W_in[k]
// Thread t owns pair base+t: full 64-ch output in 32 packed accumulators.
// ---------------------------------------------------------------------------
__global__ __launch_bounds__(64) void fused1_kernel(
    const float* __restrict__ feats, const float* __restrict__ W_in, int P)
{
    const int k    = blockIdx.y;
    const int cnt  = g_cnt[k];
    const int base = blockIdx.x * 64;
    if (base >= cnt) return;
    const int t  = threadIdx.x;
    const int nv = min(64, cnt - base);

    __shared__ float  sx[64 * 33];      // gathered x rows, pad 33 (conflict-free)
    __shared__ float2 sw[CIN * 32];     // W_in[k] as [c][d2]
    __shared__ uint2  sp[64];           // pair list tile

    {
        const float2* Wk = reinterpret_cast<const float2*>(W_in + (size_t)k * CIN * CMID);
        for (int i = t; i < CIN * 32; i += 64) sw[i] = Wk[i];
    }
    sp[t] = (t < nv) ? g_pairs[(size_t)k * MAXP + base + t] : make_uint2(0u, 0u);
    __syncthreads();

    // Gather 64 rows x 32 floats: 8 consecutive lanes load one 128B row.
    for (int i = t; i < 64 * 8; i += 64) {
        const int r = i >> 3, q = i & 7;
        float4 v = reinterpret_cast<const float4*>(feats + (size_t)sp[r].x * CIN)[q];
        float* d = sx + r * 33 + q * 4;
        d[0] = v.x; d[1] = v.y; d[2] = v.z; d[3] = v.w;
    }
    __syncthreads();

    unsigned long long acc[32];
#pragma unroll
    for (int i = 0; i < 32; i++) acc[i] = 0ull;

    const float* xr = sx + t * 33;
#pragma unroll
    for (int c = 0; c < 32; c++) {
        const float xc = xr[c];
        const unsigned long long a = pk2(xc, xc);
        const ulonglong2* wrow = reinterpret_cast<const ulonglong2*>(sw + c * 32);
#pragma unroll
        for (int d = 0; d < 16; d++) {
            ulonglong2 w2 = wrow[d];
            acc[2 * d]     = fma2(a, w2.x, acc[2 * d]);
            acc[2 * d + 1] = fma2(a, w2.y, acc[2 * d + 1]);
        }
    }

    if (t < nv) {
        float* dst = g_h + (size_t)sp[t].y * CMID;
#pragma unroll
        for (int d = 0; d < 16; d++) {
            float2 lo = upk2(acc[2 * d]);
            float2 hi = upk2(acc[2 * d + 1]);
            red_add_v4(dst + d * 4, make_float4(lo.x, lo.y, hi.x, hi.y));
        }
    }
}

// ---------------------------------------------------------------------------
// Fused layer 2: out[vout][0:32] += relu(g_h[vin][0:64]) @ W_out[k]
// ---------------------------------------------------------------------------
__global__ __launch_bounds__(64) void fused2_kernel(
    const float* __restrict__ W_out, float* __restrict__ out, int P)
{
    const int k    = blockIdx.y;
    const int cnt  = g_cnt[k];
    const int base = blockIdx.x * 64;
    if (base >= cnt) return;
    const int t  = threadIdx.x;
    const int nv = min(64, cnt - base);

    __shared__ float  sx[64 * 65];      // gathered relu(h) rows, pad 65
    __shared__ float2 sw[CMID * 16];    // W_out[k] as [c][d2]
    __shared__ uint2  sp[64];

    {
        const float2* Wk = reinterpret_cast<const float2*>(W_out + (size_t)k * CMID * COUT);
        for (int i = t; i < CMID * 16; i += 64) sw[i] = Wk[i];
    }
    sp[t] = (t < nv) ? g_pairs[(size_t)k * MAXP + base + t] : make_uint2(0u, 0u);
    __syncthreads();

    // Gather 64 rows x 64 floats: 16 consecutive lanes load one 256B row. ReLU fused.
    for (int i = t; i < 64 * 16; i += 64) {
        const int r = i >> 4, q = i & 15;
        float4 v = reinterpret_cast<const float4*>(g_h + (size_t)sp[r].x * CMID)[q];
        float* d = sx + r * 65 + q * 4;
        d[0] = fmaxf(v.x, 0.f); d[1] = fmaxf(v.y, 0.f);
        d[2] = fmaxf(v.z, 0.f); d[3] = fmaxf(v.w, 0.f);
    }
    __syncthreads();

    unsigned long long acc[16];
#pragma unroll
    for (int i = 0; i < 16; i++) acc[i] = 0ull;

    const float* xr = sx + t * 65;
#pragma unroll
    for (int c = 0; c < 64; c++) {
        const float xc = xr[c];
        const unsigned long long a = pk2(xc, xc);
        const ulonglong2* wrow = reinterpret_cast<const ulonglong2*>(sw + c * 16);
#pragma unroll
        for (int d = 0; d < 8; d++) {
            ulonglong2 w2 = wrow[d];
            acc[2 * d]     = fma2(a, w2.x, acc[2 * d]);
            acc[2 * d + 1] = fma2(a, w2.y, acc[2 * d + 1]);
        }
    }

    if (t < nv) {
        float* dst = out + (size_t)sp[t].y * COUT;
#pragma unroll
        for (int d = 0; d < 8; d++) {
            float2 lo = upk2(acc[2 * d]);
            float2 hi = upk2(acc[2 * d + 1]);
            red_add_v4(dst + d * 4, make_float4(lo.x, lo.y, hi.x, hi.y));
        }
    }
}

// ---------------------------------------------------------------------------
// Inputs: feats f32[N,32], nbr_in_idx i32[K,P], nbr_out_idx i32[K,P],
// nbr_mask f32[K,P], W_in f32[K,32,64], W_out f32[K,64,32]. Output f32[N,32].
// ---------------------------------------------------------------------------
extern "C" void kernel_launch(void* const* d_in, const int* in_sizes, int n_in,
                              void* d_out, int out_size) {
    const float* feats   = (const float*)d_in[0];
    const int*   in_idx  = (const int*)  d_in[1];
    const int*   out_idx = (const int*)  d_in[2];
    const float* mask    = (const float*)d_in[3];
    const float* W_in    = (const float*)d_in[4];
    const float* W_out   = (const float*)d_in[5];
    float*       out     = (float*)      d_out;

    const int N = in_sizes[0] / CIN;
    const int K = in_sizes[4] / (CIN * CMID);
    const int P = in_sizes[3] / K;

    const int n_out4 = N * COUT / 4;
    const int n_h4   = N * CMID / 4;
    const int nmax   = (n_out4 > n_h4) ? n_out4 : n_h4;
    zero_kernel<<<(nmax + 255) / 256, 256>>>((float4*)out, n_out4, n_h4);

    dim3 gc((P + 255) / 256, K);
    compact_kernel<<<gc, 256>>>(in_idx, out_idx, mask, P);

    dim3 gf((P + 63) / 64, K);
    fused1_kernel<<<gf, 64>>>(feats, W_in, P);
    fused2_kernel<<<gf, 64>>>(W_out, out, P);
}

// round 7
// speedup vs baseline: 2.0198x; 1.3074x over previous
#include <cuda_runtime.h>
#include <cstdint>

// ----------------------------------------------------------------------------
// Fused sparse conv, register-tiled: block = 128 pairs of one offset k.
// Thread (dcol = t&3, prow = t>>2) computes 4 pairs x 16 (or 8) out-channels,
// so each weight smem load is amortized over 4 pairs (fma:LDS ~ 4:1).
//   gather x rows -> smem -> 4x16 register GEMM tile (f32x2) -> red.v4 scatter
// ----------------------------------------------------------------------------

constexpr int CIN   = 32;
constexpr int CMID  = 64;
constexpr int COUT  = 32;
constexpr int MAXN  = 200192;
constexpr int MAXK  = 27;
constexpr int MAXP  = 400000;
constexpr int PT    = 128;        // pairs per block

__device__ float g_h[(size_t)MAXN * CMID];        // 51 MB hidden layer
__device__ uint2 g_pairs[(size_t)MAXK * MAXP];    // 86 MB per-k pair segments
__device__ int   g_cnt[MAXK];

static __device__ __forceinline__ unsigned long long pk2(float x, float y) {
    unsigned long long r;
    asm("mov.b64 %0, {%1, %2};" : "=l"(r) : "f"(x), "f"(y));
    return r;
}
static __device__ __forceinline__ float2 upk2(unsigned long long v) {
    float2 f;
    asm("mov.b64 {%0, %1}, %2;" : "=f"(f.x), "=f"(f.y) : "l"(v));
    return f;
}
static __device__ __forceinline__ unsigned long long fma2(
    unsigned long long a, unsigned long long b, unsigned long long c) {
    unsigned long long d;
    asm("fma.rn.f32x2 %0, %1, %2, %3;" : "=l"(d) : "l"(a), "l"(b), "l"(c));
    return d;
}
static __device__ __forceinline__ void red_add_v4(float* p, float4 v) {
    asm volatile("red.global.add.v4.f32 [%0], {%1, %2, %3, %4};"
                 :: "l"(p), "f"(v.x), "f"(v.y), "f"(v.z), "f"(v.w) : "memory");
}

// ---------------------------------------------------------------------------
__global__ void zero_kernel(float4* __restrict__ out, int n_out4, int n_h4) {
    int i = blockIdx.x * blockDim.x + threadIdx.x;
    float4 z = make_float4(0.f, 0.f, 0.f, 0.f);
    if (i < n_out4) out[i] = z;
    if (i < n_h4) reinterpret_cast<float4*>(g_h)[i] = z;
    if (i < MAXK) g_cnt[i] = 0;
}

// ---------------------------------------------------------------------------
// Compact valid pairs into per-k segments (warp-aggregated atomic).
// ---------------------------------------------------------------------------
__global__ __launch_bounds__(256) void compact_kernel(
    const int* __restrict__ in_idx, const int* __restrict__ out_idx,
    const float* __restrict__ mask, int P)
{
    const int k = blockIdx.y;
    const int p = blockIdx.x * blockDim.x + threadIdx.x;
    bool v = false; int vin = 0, vout = 0;
    if (p < P) {
        size_t o = (size_t)k * P + p;
        v = mask[o] > 0.5f;
        if (v) { vin = in_idx[o]; vout = out_idx[o]; }
    }
    unsigned b = __ballot_sync(0xffffffffu, v);
    int cnt = __popc(b);
    if (cnt == 0) return;
    const int lane = threadIdx.x & 31;
    const int leader = __ffs(b) - 1;
    int base = 0;
    if (lane == leader) base = atomicAdd(&g_cnt[k], cnt);
    base = __shfl_sync(0xffffffffu, base, leader);
    if (v) {
        int off = __popc(b & ((1u << lane) - 1u));
        g_pairs[(size_t)k * MAXP + base + off] =
            make_uint2((unsigned)vin, (unsigned)vout);
    }
}

// ---------------------------------------------------------------------------
// Fused layer 1: g_h[vout][0:64] += feats[vin][0:32] @ W_in[k]
// 128 threads, 128 pairs. Thread: dcol = t&3 (16 out-ch), prow = t>>2,
// pairs {prow + 32j}. Per c: 4 w-LDS.128 + 4 x-LDS, 32 fma2.
// ---------------------------------------------------------------------------
__global__ __launch_bounds__(128) void fused1_kernel(
    const float* __restrict__ feats, const float* __restrict__ W_in, int P)
{
    const int k    = blockIdx.y;
    const int cnt  = g_cnt[k];
    const int base = blockIdx.x * PT;
    if (base >= cnt) return;
    const int t  = threadIdx.x;
    const int nv = min(PT, cnt - base);

    __shared__ float  sx[PT * 33];       // gathered x rows (pad 33)
    __shared__ float2 sw[CIN * 32];      // W_in[k]: [c][d2], row = 32 u64
    __shared__ uint2  sp[PT];

    {
        const float2* Wk = reinterpret_cast<const float2*>(W_in + (size_t)k * CIN * CMID);
        for (int i = t; i < CIN * 32; i += 128) sw[i] = Wk[i];
    }
    if (t < PT) sp[t] = (t < nv) ? g_pairs[(size_t)k * MAXP + base + t]
                                 : make_uint2(0u, 0u);
    __syncthreads();

    // Gather 128 rows x 32 floats: 8 lanes per 128B row.
    for (int i = t; i < PT * 8; i += 128) {
        const int r = i >> 3, q = i & 7;
        float4 v = reinterpret_cast<const float4*>(feats + (size_t)sp[r].x * CIN)[q];
        float* d = sx + r * 33 + q * 4;
        d[0] = v.x; d[1] = v.y; d[2] = v.z; d[3] = v.w;
    }
    __syncthreads();

    const int dcol = t & 3;              // 4 groups of 16 out-channels
    const int prow = t >> 2;             // 0..31

    unsigned long long acc[4][8];
#pragma unroll
    for (int j = 0; j < 4; j++)
#pragma unroll
        for (int d = 0; d < 8; d++) acc[j][d] = 0ull;

#pragma unroll
    for (int c = 0; c < 32; c++) {
        const ulonglong2* wrow = reinterpret_cast<const ulonglong2*>(sw + c * 32)
                                 + dcol * 4;
        ulonglong2 w0 = wrow[0], w1 = wrow[1], w2 = wrow[2], w3 = wrow[3];
        unsigned long long a[4];
#pragma unroll
        for (int j = 0; j < 4; j++) {
            float xc = sx[(prow + 32 * j) * 33 + c];
            a[j] = pk2(xc, xc);
        }
#pragma unroll
        for (int j = 0; j < 4; j++) {
            acc[j][0] = fma2(a[j], w0.x, acc[j][0]);
            acc[j][1] = fma2(a[j], w0.y, acc[j][1]);
            acc[j][2] = fma2(a[j], w1.x, acc[j][2]);
            acc[j][3] = fma2(a[j], w1.y, acc[j][3]);
            acc[j][4] = fma2(a[j], w2.x, acc[j][4]);
            acc[j][5] = fma2(a[j], w2.y, acc[j][5]);
            acc[j][6] = fma2(a[j], w3.x, acc[j][6]);
            acc[j][7] = fma2(a[j], w3.y, acc[j][7]);
        }
    }

#pragma unroll
    for (int j = 0; j < 4; j++) {
        const int p = prow + 32 * j;
        if (p < nv) {
            float* dst = g_h + (size_t)sp[p].y * CMID + dcol * 16;
#pragma unroll
            for (int d = 0; d < 4; d++) {
                float2 lo = upk2(acc[j][2 * d]);
                float2 hi = upk2(acc[j][2 * d + 1]);
                red_add_v4(dst + d * 4, make_float4(lo.x, lo.y, hi.x, hi.y));
            }
        }
    }
}

// ---------------------------------------------------------------------------
// Fused layer 2: out[vout][0:32] += relu(g_h[vin][0:64]) @ W_out[k]
// Thread: dcol = t&3 (8 out-ch), prow = t>>2, pairs {prow + 32j}.
// ---------------------------------------------------------------------------
__global__ __launch_bounds__(128) void fused2_kernel(
    const float* __restrict__ W_out, float* __restrict__ out, int P)
{
    const int k    = blockIdx.y;
    const int cnt  = g_cnt[k];
    const int base = blockIdx.x * PT;
    if (base >= cnt) return;
    const int t  = threadIdx.x;
    const int nv = min(PT, cnt - base);

    __shared__ float  sx[PT * 65];       // gathered relu(h) rows (pad 65)
    __shared__ float2 sw[CMID * 16];     // W_out[k]: [c][d2], row = 16 u64
    __shared__ uint2  sp[PT];

    {
        const float2* Wk = reinterpret_cast<const float2*>(W_out + (size_t)k * CMID * COUT);
        for (int i = t; i < CMID * 16; i += 128) sw[i] = Wk[i];
    }
    if (t < PT) sp[t] = (t < nv) ? g_pairs[(size_t)k * MAXP + base + t]
                                 : make_uint2(0u, 0u);
    __syncthreads();

    // Gather 128 rows x 64 floats: 16 lanes per 256B row. ReLU fused.
    for (int i = t; i < PT * 16; i += 128) {
        const int r = i >> 4, q = i & 15;
        float4 v = reinterpret_cast<const float4*>(g_h + (size_t)sp[r].x * CMID)[q];
        float* d = sx + r * 65 + q * 4;
        d[0] = fmaxf(v.x, 0.f); d[1] = fmaxf(v.y, 0.f);
        d[2] = fmaxf(v.z, 0.f); d[3] = fmaxf(v.w, 0.f);
    }
    __syncthreads();

    const int dcol = t & 3;              // 4 groups of 8 out-channels
    const int prow = t >> 2;

    unsigned long long acc[4][4];
#pragma unroll
    for (int j = 0; j < 4; j++)
#pragma unroll
        for (int d = 0; d < 4; d++) acc[j][d] = 0ull;

#pragma unroll
    for (int c = 0; c < 64; c++) {
        const ulonglong2* wrow = reinterpret_cast<const ulonglong2*>(sw + c * 16)
                                 + dcol * 2;
        ulonglong2 w0 = wrow[0], w1 = wrow[1];
        unsigned long long a[4];
#pragma unroll
        for (int j = 0; j < 4; j++) {
            float xc = sx[(prow + 32 * j) * 65 + c];
            a[j] = pk2(xc, xc);
        }
#pragma unroll
        for (int j = 0; j < 4; j++) {
            acc[j][0] = fma2(a[j], w0.x, acc[j][0]);
            acc[j][1] = fma2(a[j], w0.y, acc[j][1]);
            acc[j][2] = fma2(a[j], w1.x, acc[j][2]);
            acc[j][3] = fma2(a[j], w1.y, acc[j][3]);
        }
    }

#pragma unroll
    for (int j = 0; j < 4; j++) {
        const int p = prow + 32 * j;
        if (p < nv) {
            float* dst = out + (size_t)sp[p].y * COUT + dcol * 8;
#pragma unroll
            for (int d = 0; d < 2; d++) {
                float2 lo = upk2(acc[j][2 * d]);
                float2 hi = upk2(acc[j][2 * d + 1]);
                red_add_v4(dst + d * 4, make_float4(lo.x, lo.y, hi.x, hi.y));
            }
        }
    }
}

// ---------------------------------------------------------------------------
// Inputs: feats f32[N,32], nbr_in_idx i32[K,P], nbr_out_idx i32[K,P],
// nbr_mask f32[K,P], W_in f32[K,32,64], W_out f32[K,64,32]. Output f32[N,32].
// ---------------------------------------------------------------------------
extern "C" void kernel_launch(void* const* d_in, const int* in_sizes, int n_in,
                              void* d_out, int out_size) {
    const float* feats   = (const float*)d_in[0];
    const int*   in_idx  = (const int*)  d_in[1];
    const int*   out_idx = (const int*)  d_in[2];
    const float* mask    = (const float*)d_in[3];
    const float* W_in    = (const float*)d_in[4];
    const float* W_out   = (const float*)d_in[5];
    float*       out     = (float*)      d_out;

    const int N = in_sizes[0] / CIN;
    const int K = in_sizes[4] / (CIN * CMID);
    const int P = in_sizes[3] / K;

    const int n_out4 = N * COUT / 4;
    const int n_h4   = N * CMID / 4;
    const int nmax   = (n_out4 > n_h4) ? n_out4 : n_h4;
    zero_kernel<<<(nmax + 255) / 256, 256>>>((float4*)out, n_out4, n_h4);

    dim3 gc((P + 255) / 256, K);
    compact_kernel<<<gc, 256>>>(in_idx, out_idx, mask, P);

    dim3 gf((P + PT - 1) / PT, K);
    fused1_kernel<<<gf, 128>>>(feats, W_in, P);
    fused2_kernel<<<gf, 128>>>(W_out, out, P);
}

// round 8
// speedup vs baseline: 2.0677x; 1.0237x over previous
#include <cuda_runtime.h>
#include <cstdint>

// ----------------------------------------------------------------------------
// Fused sparse conv on the TENSOR pipe: per block = 128 pairs of one offset k.
//   gather x -> hi/lo tf32 smem planes -> mma.sync.m16n8k8 (3xTF32, fp32-acc)
//   -> stage C tile in smem -> red.global.add.v4 scatter.
// 3xTF32 (hi*hi + hi*lo + lo*hi) restores ~fp32 accuracy (~1e-6 rel).
// ----------------------------------------------------------------------------

constexpr int CIN   = 32;
constexpr int CMID  = 64;
constexpr int COUT  = 32;
constexpr int MAXN  = 200192;
constexpr int MAXK  = 27;
constexpr int MAXP  = 400000;
constexpr int PT    = 128;       // pairs per block

// smem strides (floats), chosen for conflict-free fragment loads:
constexpr int SX1 = 36;   // layer1 x plane:  (4*gid+tig) covers 32 banks
constexpr int SW1 = 72;   // layer1 W plane:  (8*tig+gid) covers 32 banks
constexpr int SO1 = 68;   // layer1 C tile:   multiple of 4 (16B-aligned float4)
constexpr int SX2 = 68;   // layer2 x plane
constexpr int SW2 = 40;   // layer2 W plane
constexpr int SO2 = 36;   // layer2 C tile

constexpr int POOL1 = 2 * PT * SX1 + 2 * CIN  * SW1;   // 13824 floats (54 KB)
constexpr int POOL2 = 2 * PT * SX2 + 2 * CMID * SW2;   // 22528 floats (88 KB)

__device__ float g_h[(size_t)MAXN * CMID];        // 51 MB hidden layer
__device__ uint2 g_pairs[(size_t)MAXK * MAXP];    // 86 MB per-k pair segments
__device__ int   g_cnt[MAXK];

static __device__ __forceinline__ unsigned f2tf(float x) {
    unsigned r; asm("cvt.rna.tf32.f32 %0, %1;" : "=r"(r) : "f"(x)); return r;
}
static __device__ __forceinline__ void mma_tf32(
    float4& c, unsigned a0, unsigned a1, unsigned a2, unsigned a3,
    unsigned b0, unsigned b1)
{
    asm volatile(
        "mma.sync.aligned.m16n8k8.row.col.f32.tf32.tf32.f32 "
        "{%0,%1,%2,%3}, {%4,%5,%6,%7}, {%8,%9}, {%0,%1,%2,%3};"
        : "+f"(c.x), "+f"(c.y), "+f"(c.z), "+f"(c.w)
        : "r"(a0), "r"(a1), "r"(a2), "r"(a3), "r"(b0), "r"(b1));
}
static __device__ __forceinline__ void red_add_v4(float* p, float4 v) {
    asm volatile("red.global.add.v4.f32 [%0], {%1, %2, %3, %4};"
                 :: "l"(p), "f"(v.x), "f"(v.y), "f"(v.z), "f"(v.w) : "memory");
}
// Decompose x into tf32 hi/lo planes (stored as float bit-patterns).
static __device__ __forceinline__ void hilo(float x, float& h, float& l) {
    h = __uint_as_float(f2tf(x));
    l = __uint_as_float(f2tf(x - h));
}

// ---------------------------------------------------------------------------
__global__ void zero_kernel(float4* __restrict__ out, int n_out4, int n_h4) {
    int i = blockIdx.x * blockDim.x + threadIdx.x;
    float4 z = make_float4(0.f, 0.f, 0.f, 0.f);
    if (i < n_out4) out[i] = z;
    if (i < n_h4) reinterpret_cast<float4*>(g_h)[i] = z;
    if (i < MAXK) g_cnt[i] = 0;
}

// ---------------------------------------------------------------------------
__global__ __launch_bounds__(256) void compact_kernel(
    const int* __restrict__ in_idx, const int* __restrict__ out_idx,
    const float* __restrict__ mask, int P)
{
    const int k = blockIdx.y;
    const int p = blockIdx.x * blockDim.x + threadIdx.x;
    bool v = false; int vin = 0, vout = 0;
    if (p < P) {
        size_t o = (size_t)k * P + p;
        v = mask[o] > 0.5f;
        if (v) { vin = in_idx[o]; vout = out_idx[o]; }
    }
    unsigned b = __ballot_sync(0xffffffffu, v);
    int cnt = __popc(b);
    if (cnt == 0) return;
    const int lane = threadIdx.x & 31;
    const int leader = __ffs(b) - 1;
    int base = 0;
    if (lane == leader) base = atomicAdd(&g_cnt[k], cnt);
    base = __shfl_sync(0xffffffffu, base, leader);
    if (v) {
        int off = __popc(b & ((1u << lane) - 1u));
        g_pairs[(size_t)k * MAXP + base + off] =
            make_uint2((unsigned)vin, (unsigned)vout);
    }
}

// ---------------------------------------------------------------------------
// Fused layer 1: g_h[vout][0:64] += feats[vin][0:32] @ W_in[k]
// 256 threads / 8 warps; warp w owns pair-rows [16w,16w+16); N=64 (8 n-tiles),
// K=32 (4 k-steps). 3 MMA per (ks,nt) for 3xTF32.
// ---------------------------------------------------------------------------
__global__ __launch_bounds__(256) void fused1_kernel(
    const float* __restrict__ feats, const float* __restrict__ W_in, int P)
{
    const int k    = blockIdx.y;
    const int cnt  = g_cnt[k];
    const int base = blockIdx.x * PT;
    if (base >= cnt) return;
    const int t    = threadIdx.x;
    const int lane = t & 31;
    const int wrp  = t >> 5;
    const int nv   = min(PT, cnt - base);

    extern __shared__ float pool[];
    float* sxh = pool;                     // [PT][SX1]
    float* sxl = pool + PT * SX1;
    float* swh = pool + 2 * PT * SX1;      // [CIN][SW1]
    float* swl = swh + CIN * SW1;
    float* so  = pool;                     // aliases x planes: [PT][SO1]
    __shared__ uint2 sp[PT];

    if (t < PT) sp[t] = (t < nv) ? g_pairs[(size_t)k * MAXP + base + t]
                                 : make_uint2(0u, 0u);
    // stage W hi/lo
    for (int i = t; i < CIN * CMID; i += 256) {
        int c = i >> 6, d = i & 63;
        float h, l; hilo(W_in[(size_t)k * CIN * CMID + i], h, l);
        swh[c * SW1 + d] = h; swl[c * SW1 + d] = l;
    }
    __syncthreads();
    // gather x hi/lo (8 lanes per 128B row)
    for (int i = t; i < PT * 8; i += 256) {
        const int r = i >> 3, q = i & 7;
        float4 v = reinterpret_cast<const float4*>(feats + (size_t)sp[r].x * CIN)[q];
        float* dh = sxh + r * SX1 + q * 4;
        float* dl = sxl + r * SX1 + q * 4;
        hilo(v.x, dh[0], dl[0]); hilo(v.y, dh[1], dl[1]);
        hilo(v.z, dh[2], dl[2]); hilo(v.w, dh[3], dl[3]);
    }
    __syncthreads();

    const int gid = lane >> 2, tig = lane & 3;
    const int r0  = 16 * wrp + gid;        // A rows r0, r0+8

    float4 acc[8];
#pragma unroll
    for (int nt = 0; nt < 8; nt++) acc[nt] = make_float4(0.f, 0.f, 0.f, 0.f);

#pragma unroll
    for (int ks = 0; ks < 4; ks++) {
        const int ka = ks * 8;
        const float* ph = sxh + r0 * SX1 + ka;
        const float* pl = sxl + r0 * SX1 + ka;
        unsigned ah0 = __float_as_uint(ph[tig]);
        unsigned ah1 = __float_as_uint(ph[8 * SX1 + tig]);
        unsigned ah2 = __float_as_uint(ph[tig + 4]);
        unsigned ah3 = __float_as_uint(ph[8 * SX1 + tig + 4]);
        unsigned al0 = __float_as_uint(pl[tig]);
        unsigned al1 = __float_as_uint(pl[8 * SX1 + tig]);
        unsigned al2 = __float_as_uint(pl[tig + 4]);
        unsigned al3 = __float_as_uint(pl[8 * SX1 + tig + 4]);
#pragma unroll
        for (int nt = 0; nt < 8; nt++) {
            const int nc = nt * 8 + gid;
            unsigned bh0 = __float_as_uint(swh[(ka + tig) * SW1 + nc]);
            unsigned bh1 = __float_as_uint(swh[(ka + tig + 4) * SW1 + nc]);
            unsigned bl0 = __float_as_uint(swl[(ka + tig) * SW1 + nc]);
            unsigned bl1 = __float_as_uint(swl[(ka + tig + 4) * SW1 + nc]);
            mma_tf32(acc[nt], ah0, ah1, ah2, ah3, bh0, bh1);
            mma_tf32(acc[nt], ah0, ah1, ah2, ah3, bl0, bl1);
            mma_tf32(acc[nt], al0, al1, al2, al3, bh0, bh1);
        }
    }

    __syncthreads();                       // done reading x planes
#pragma unroll
    for (int nt = 0; nt < 8; nt++) {       // C: rows r0/r0+8, cols nt*8+2*tig(+1)
        const int cc = nt * 8 + 2 * tig;
        *reinterpret_cast<float2*>(so + r0 * SO1 + cc)       = make_float2(acc[nt].x, acc[nt].y);
        *reinterpret_cast<float2*>(so + (r0 + 8) * SO1 + cc) = make_float2(acc[nt].z, acc[nt].w);
    }
    __syncthreads();

    for (int i = t; i < PT * 16; i += 256) {
        const int r = i >> 4, l = i & 15;
        if (r < nv)
            red_add_v4(g_h + (size_t)sp[r].y * CMID + l * 4,
                       *reinterpret_cast<float4*>(so + r * SO1 + l * 4));
    }
}

// ---------------------------------------------------------------------------
// Fused layer 2: out[vout][0:32] += relu(g_h[vin][0:64]) @ W_out[k]
// N=32 (4 n-tiles), K=64 (8 k-steps).
// ---------------------------------------------------------------------------
__global__ __launch_bounds__(256) void fused2_kernel(
    const float* __restrict__ W_out, float* __restrict__ out, int P)
{
    const int k    = blockIdx.y;
    const int cnt  = g_cnt[k];
    const int base = blockIdx.x * PT;
    if (base >= cnt) return;
    const int t    = threadIdx.x;
    const int lane = t & 31;
    const int wrp  = t >> 5;
    const int nv   = min(PT, cnt - base);

    extern __shared__ float pool[];
    float* sxh = pool;                     // [PT][SX2]
    float* sxl = pool + PT * SX2;
    float* swh = pool + 2 * PT * SX2;      // [CMID][SW2]
    float* swl = swh + CMID * SW2;
    float* so  = pool;                     // aliases x planes: [PT][SO2]
    __shared__ uint2 sp[PT];

    if (t < PT) sp[t] = (t < nv) ? g_pairs[(size_t)k * MAXP + base + t]
                                 : make_uint2(0u, 0u);
    for (int i = t; i < CMID * COUT; i += 256) {
        int c = i >> 5, d = i & 31;
        float h, l; hilo(W_out[(size_t)k * CMID * COUT + i], h, l);
        swh[c * SW2 + d] = h; swl[c * SW2 + d] = l;
    }
    __syncthreads();
    // gather relu(h) hi/lo (16 lanes per 256B row)
    for (int i = t; i < PT * 16; i += 256) {
        const int r = i >> 4, q = i & 15;
        float4 v = reinterpret_cast<const float4*>(g_h + (size_t)sp[r].x * CMID)[q];
        float* dh = sxh + r * SX2 + q * 4;
        float* dl = sxl + r * SX2 + q * 4;
        hilo(fmaxf(v.x, 0.f), dh[0], dl[0]); hilo(fmaxf(v.y, 0.f), dh[1], dl[1]);
        hilo(fmaxf(v.z, 0.f), dh[2], dl[2]); hilo(fmaxf(v.w, 0.f), dh[3], dl[3]);
    }
    __syncthreads();

    const int gid = lane >> 2, tig = lane & 3;
    const int r0  = 16 * wrp + gid;

    float4 acc[4];
#pragma unroll
    for (int nt = 0; nt < 4; nt++) acc[nt] = make_float4(0.f, 0.f, 0.f, 0.f);

#pragma unroll
    for (int ks = 0; ks < 8; ks++) {
        const int ka = ks * 8;
        const float* ph = sxh + r0 * SX2 + ka;
        const float* pl = sxl + r0 * SX2 + ka;
        unsigned ah0 = __float_as_uint(ph[tig]);
        unsigned ah1 = __float_as_uint(ph[8 * SX2 + tig]);
        unsigned ah2 = __float_as_uint(ph[tig + 4]);
        unsigned ah3 = __float_as_uint(ph[8 * SX2 + tig + 4]);
        unsigned al0 = __float_as_uint(pl[tig]);
        unsigned al1 = __float_as_uint(pl[8 * SX2 + tig]);
        unsigned al2 = __float_as_uint(pl[tig + 4]);
        unsigned al3 = __float_as_uint(pl[8 * SX2 + tig + 4]);
#pragma unroll
        for (int nt = 0; nt < 4; nt++) {
            const int nc = nt * 8 + gid;
            unsigned bh0 = __float_as_uint(swh[(ka + tig) * SW2 + nc]);
            unsigned bh1 = __float_as_uint(swh[(ka + tig + 4) * SW2 + nc]);
            unsigned bl0 = __float_as_uint(swl[(ka + tig) * SW2 + nc]);
            unsigned bl1 = __float_as_uint(swl[(ka + tig + 4) * SW2 + nc]);
            mma_tf32(acc[nt], ah0, ah1, ah2, ah3, bh0, bh1);
            mma_tf32(acc[nt], ah0, ah1, ah2, ah3, bl0, bl1);
            mma_tf32(acc[nt], al0, al1, al2, al3, bh0, bh1);
        }
    }

    __syncthreads();
#pragma unroll
    for (int nt = 0; nt < 4; nt++) {
        const int cc = nt * 8 + 2 * tig;
        *reinterpret_cast<float2*>(so + r0 * SO2 + cc)       = make_float2(acc[nt].x, acc[nt].y);
        *reinterpret_cast<float2*>(so + (r0 + 8) * SO2 + cc) = make_float2(acc[nt].z, acc[nt].w);
    }
    __syncthreads();

    for (int i = t; i < PT * 8; i += 256) {
        const int r = i >> 3, l = i & 7;
        if (r < nv)
            red_add_v4(out + (size_t)sp[r].y * COUT + l * 4,
                       *reinterpret_cast<float4*>(so + r * SO2 + l * 4));
    }
}

// ---------------------------------------------------------------------------
// Inputs: feats f32[N,32], nbr_in_idx i32[K,P], nbr_out_idx i32[K,P],
// nbr_mask f32[K,P], W_in f32[K,32,64], W_out f32[K,64,32]. Output f32[N,32].
// ---------------------------------------------------------------------------
extern "C" void kernel_launch(void* const* d_in, const int* in_sizes, int n_in,
                              void* d_out, int out_size) {
    const float* feats   = (const float*)d_in[0];
    const int*   in_idx  = (const int*)  d_in[1];
    const int*   out_idx = (const int*)  d_in[2];
    const float* mask    = (const float*)d_in[3];
    const float* W_in    = (const float*)d_in[4];
    const float* W_out   = (const float*)d_in[5];
    float*       out     = (float*)      d_out;

    const int N = in_sizes[0] / CIN;
    const int K = in_sizes[4] / (CIN * CMID);
    const int P = in_sizes[3] / K;

    const int smem1 = POOL1 * (int)sizeof(float);   // ~54 KB
    const int smem2 = POOL2 * (int)sizeof(float);   // ~88 KB
    cudaFuncSetAttribute(fused1_kernel,
        cudaFuncAttributeMaxDynamicSharedMemorySize, smem1);
    cudaFuncSetAttribute(fused2_kernel,
        cudaFuncAttributeMaxDynamicSharedMemorySize, smem2);

    const int n_out4 = N * COUT / 4;
    const int n_h4   = N * CMID / 4;
    const int nmax   = (n_out4 > n_h4) ? n_out4 : n_h4;
    zero_kernel<<<(nmax + 255) / 256, 256>>>((float4*)out, n_out4, n_h4);

    dim3 gc((P + 255) / 256, K);
    compact_kernel<<<gc, 256>>>(in_idx, out_idx, mask, P);

    dim3 gf((P + PT - 1) / PT, K);
    fused1_kernel<<<gf, 256, smem1>>>(feats, W_in, P);
    fused2_kernel<<<gf, 256, smem2>>>(W_out, out, P);
}